// round 1
// baseline (speedup 1.0000x reference)
#include <cuda_runtime.h>
#include <cstdint>

#define LVAL 4096
#define NB 64
#define ROWS_CTA 64
#define KC 64
#define STRIDE 68   // 64 + 4 pad, conflict-free LDS
#define RADIUS 0.9f

// Blaschke basis matrix B[n][l], fp32, built once per launch (L2-resident, 1 MB)
__device__ float g_B[NB * LVAL];

__global__ void build_B_kernel() {
    int idx = blockIdx.x * blockDim.x + threadIdx.x;
    if (idx >= NB * LVAL) return;
    int n = idx >> 12;      // / 4096
    int l = idx & 4095;
    const double TWO_PI = 6.283185307179586476925286766559;
    float theta = (float)((double)n * (TWO_PI / 64.0));
    float t     = (float)((double)l * (TWO_PI / 4095.0));   // linspace(0,2pi,4096) endpoint
    float c = cosf(t - theta);
    const float r = RADIUS;
    float scale = sqrtf(1.0f - r * r);
    g_B[idx] = scale * (1.0f - r * c) / (1.0f - 2.0f * r * c + r * r);
}

__device__ __forceinline__ uint32_t f2tf(float f) {
    uint32_t r; asm("cvt.rna.tf32.f32 %0, %1;" : "=r"(r) : "f"(f)); return r;
}
__device__ __forceinline__ float f2tff(float f) { return __uint_as_float(f2tf(f)); }

// D = A(16x8,row) * B(8x8,col) + D, tf32 inputs (pre-rounded), fp32 accum
__device__ __forceinline__ void mma8(float* c, const uint32_t* a, const uint32_t* b) {
    asm volatile(
        "mma.sync.aligned.m16n8k8.row.col.f32.tf32.tf32.f32 "
        "{%0,%1,%2,%3}, {%4,%5,%6,%7}, {%8,%9}, {%0,%1,%2,%3};\n"
        : "+f"(c[0]), "+f"(c[1]), "+f"(c[2]), "+f"(c[3])
        : "r"(a[0]), "r"(a[1]), "r"(a[2]), "r"(a[3]),
          "r"(b[0]), "r"(b[1]));
}

__global__ __launch_bounds__(128) void afd_fused_kernel(
    const float* __restrict__ x, float* __restrict__ out)
{
    __shared__ float sbuf[2 * NB * STRIDE];   // 8704 floats = 34816 B (static)
    float* s0 = sbuf;                // phase A: x chunk [64][68]; later proj/W [row][n]
    float* s1 = sbuf + NB * STRIDE;  // B chunk [64][68]

    const int tid  = threadIdx.x;
    const int warp = tid >> 5;
    const int lane = tid & 31;
    const int g    = lane >> 2;      // groupID
    const int tig  = lane & 3;       // thread in group
    const int row0 = blockIdx.x * ROWS_CTA;
    const int mo = (warp & 1) * 32;  // phase A: basis offset | phase C: row offset
    const int no = (warp >> 1) * 32; // phase A: row offset   | phase C: l offset

    float acc[8][4];
    #pragma unroll
    for (int i = 0; i < 8; i++)
        #pragma unroll
        for (int j = 0; j < 4; j++) acc[i][j] = 0.f;

    // ================= Phase A: proj[basis, row] = sum_l B[basis,l] * x[row,l] ======
    for (int k0 = 0; k0 < LVAL; k0 += KC) {
        #pragma unroll
        for (int i = 0; i < 8; i++) {
            int idx = tid + i * 128;
            int r = idx >> 4, q = idx & 15;
            float4 v = *(const float4*)(x + (size_t)(row0 + r) * LVAL + k0 + q * 4);
            *(float4*)(s0 + r * STRIDE + q * 4) =
                make_float4(f2tff(v.x), f2tff(v.y), f2tff(v.z), f2tff(v.w));
            float4 u = *(const float4*)(g_B + (size_t)r * LVAL + k0 + q * 4);
            *(float4*)(s1 + r * STRIDE + q * 4) =
                make_float4(f2tff(u.x), f2tff(u.y), f2tff(u.z), f2tff(u.w));
        }
        __syncthreads();

        #pragma unroll
        for (int kk = 0; kk < KC; kk += 8) {
            uint32_t a[2][4], b[4][2];
            #pragma unroll
            for (int mt = 0; mt < 2; mt++) {
                const float* ap = s1 + (mo + mt * 16 + g) * STRIDE + kk + tig;
                a[mt][0] = __float_as_uint(ap[0]);
                a[mt][1] = __float_as_uint(ap[8 * STRIDE]);
                a[mt][2] = __float_as_uint(ap[4]);
                a[mt][3] = __float_as_uint(ap[8 * STRIDE + 4]);
            }
            #pragma unroll
            for (int nt = 0; nt < 4; nt++) {
                const float* bp = s0 + (no + nt * 8 + g) * STRIDE + kk + tig;
                b[nt][0] = __float_as_uint(bp[0]);
                b[nt][1] = __float_as_uint(bp[4]);
            }
            #pragma unroll
            for (int mt = 0; mt < 2; mt++)
                #pragma unroll
                for (int nt = 0; nt < 4; nt++)
                    mma8(acc[mt * 4 + nt], a[mt], b[nt]);
        }
        __syncthreads();
    }

    // ================= Phase B: dump proj to smem [row][basis], softmax(|.|) =======
    #pragma unroll
    for (int mt = 0; mt < 2; mt++)
        #pragma unroll
        for (int nt = 0; nt < 4; nt++) {
            int basis = mo + mt * 16 + g;
            int rr    = no + nt * 8 + 2 * tig;
            s0[(rr    ) * STRIDE + basis    ] = acc[mt * 4 + nt][0];
            s0[(rr + 1) * STRIDE + basis    ] = acc[mt * 4 + nt][1];
            s0[(rr    ) * STRIDE + basis + 8] = acc[mt * 4 + nt][2];
            s0[(rr + 1) * STRIDE + basis + 8] = acc[mt * 4 + nt][3];
        }
    __syncthreads();

    for (int r = warp * 16; r < warp * 16 + 16; r++) {
        float v0 = fabsf(s0[r * STRIDE + lane]);
        float v1 = fabsf(s0[r * STRIDE + lane + 32]);
        float m = fmaxf(v0, v1);
        #pragma unroll
        for (int o = 16; o > 0; o >>= 1) m = fmaxf(m, __shfl_xor_sync(0xffffffffu, m, o));
        float e0 = __expf(v0 - m), e1 = __expf(v1 - m);
        float s = e0 + e1;
        #pragma unroll
        for (int o = 16; o > 0; o >>= 1) s += __shfl_xor_sync(0xffffffffu, s, o);
        float inv = 1.0f / s;
        s0[r * STRIDE + lane     ] = f2tff(e0 * inv);   // W pre-rounded to tf32
        s0[r * STRIDE + lane + 32] = f2tff(e1 * inv);
    }
    __syncthreads();

    // ================= Phase C: out[row,l] = x[row,l] + sum_n W[row,n]*B[n,l] ======
    for (int l0 = 0; l0 < LVAL; l0 += KC) {
        #pragma unroll
        for (int i = 0; i < 8; i++) {
            int idx = tid + i * 128;
            int n = idx >> 4, q = idx & 15;
            float4 u = *(const float4*)(g_B + (size_t)n * LVAL + l0 + q * 4);
            *(float4*)(s1 + n * STRIDE + q * 4) =
                make_float4(f2tff(u.x), f2tff(u.y), f2tff(u.z), f2tff(u.w));
        }
        __syncthreads();

        #pragma unroll
        for (int i = 0; i < 8; i++)
            #pragma unroll
            for (int j = 0; j < 4; j++) acc[i][j] = 0.f;

        #pragma unroll
        for (int kk = 0; kk < NB; kk += 8) {
            uint32_t a[2][4], b[4][2];
            #pragma unroll
            for (int mt = 0; mt < 2; mt++) {
                const float* ap = s0 + (mo + mt * 16 + g) * STRIDE + kk + tig;  // W[row][n]
                a[mt][0] = __float_as_uint(ap[0]);
                a[mt][1] = __float_as_uint(ap[8 * STRIDE]);
                a[mt][2] = __float_as_uint(ap[4]);
                a[mt][3] = __float_as_uint(ap[8 * STRIDE + 4]);
            }
            #pragma unroll
            for (int nt = 0; nt < 4; nt++) {
                const float* bp = s1 + (kk + tig) * STRIDE + no + nt * 8 + g;   // B[n][l]
                b[nt][0] = __float_as_uint(bp[0]);
                b[nt][1] = __float_as_uint(bp[4 * STRIDE]);
            }
            #pragma unroll
            for (int mt = 0; mt < 2; mt++)
                #pragma unroll
                for (int nt = 0; nt < 4; nt++)
                    mma8(acc[mt * 4 + nt], a[mt], b[nt]);
        }

        // epilogue: out = x + attn (x read fresh fp32, exact passthrough)
        #pragma unroll
        for (int mt = 0; mt < 2; mt++)
            #pragma unroll
            for (int nt = 0; nt < 4; nt++) {
                int row = row0 + mo + mt * 16 + g;
                int lc  = l0 + no + nt * 8 + 2 * tig;
                size_t i0 = (size_t)row * LVAL + lc;
                float2 xv = *(const float2*)(x + i0);
                *(float2*)(out + i0) =
                    make_float2(xv.x + acc[mt * 4 + nt][0], xv.y + acc[mt * 4 + nt][1]);
                size_t i1 = i0 + (size_t)8 * LVAL;
                float2 xw = *(const float2*)(x + i1);
                *(float2*)(out + i1) =
                    make_float2(xw.x + acc[mt * 4 + nt][2], xw.y + acc[mt * 4 + nt][3]);
            }
        __syncthreads();
    }
}

extern "C" void kernel_launch(void* const* d_in, const int* in_sizes, int n_in,
                              void* d_out, int out_size) {
    const float* x = (const float*)d_in[0];
    float* out = (float*)d_out;
    (void)in_sizes; (void)n_in; (void)out_size;

    build_B_kernel<<<(NB * LVAL + 255) / 256, 256>>>();
    afd_fused_kernel<<<16384 / ROWS_CTA, 128>>>(x, out);
}